// round 12
// baseline (speedup 1.0000x reference)
#include <cuda_runtime.h>
#include <cstdint>

#define EPSF 1e-7f
typedef unsigned long long u64t;

constexpr int Bb = 32;
constexpr int Ii = 32;
constexpr int Oo = 64;
constexpr int Pp = 16;
constexpr int Nn = 2048;
constexpr int CHUNKS = 16;   // 4 spatial per block
constexpr int ROWS = 128;    // 4 spatial * 32 i
constexpr int WS = 20;       // padded stride for mean/inv (conflict-free LDS128)
constexpr int AS = 17;       // padded stride for smem accumulators (conflict-free ATOMS)

// Global scratch (device globals; no cudaMalloc allowed)
__device__ float g_S0[Bb][Oo];
__device__ float g_S1[Bb][Oo][Pp];
__device__ float g_S2[Bb][Oo][Pp];
__device__ float g_mean[Bb][Oo][Pp];
__device__ float g_inv2var[Bb][Oo][Pp];
__device__ float g_ll[Bb][Oo];              // log(act+eps) - lsum (fused)
__device__ ulonglong2 g_wT2[Ii * 4 * Oo];   // W: [ic][k][o] -> {pair(c0,c1), pair(c2,c3)}
__device__ float g_rrf[(size_t)Bb * Nn * 64];  // rr: [b][n][o]

// ---- f32x2 packed helpers ----
__device__ __forceinline__ u64t pk2(float lo, float hi) {
    u64t r; asm("mov.b64 %0,{%1,%2};" : "=l"(r) : "f"(lo), "f"(hi)); return r;
}
__device__ __forceinline__ void up2(u64t a, float& lo, float& hi) {
    asm("mov.b64 {%0,%1},%2;" : "=f"(lo), "=f"(hi) : "l"(a));
}
__device__ __forceinline__ u64t fma2(u64t a, u64t b, u64t c) {
    u64t d; asm("fma.rn.f32x2 %0,%1,%2,%3;" : "=l"(d) : "l"(a), "l"(b), "l"(c)); return d;
}
__device__ __forceinline__ u64t add2(u64t a, u64t b) {
    u64t d; asm("add.rn.f32x2 %0,%1,%2;" : "=l"(d) : "l"(a), "l"(b)); return d;
}
__device__ __forceinline__ u64t mul2(u64t a, u64t b) {
    u64t d; asm("mul.rn.f32x2 %0,%1,%2;" : "=l"(d) : "l"(a), "l"(b)); return d;
}
// ---- warp reductions (redux.sync.f32 not in sm_103 ISA) ----
__device__ __forceinline__ float warp_max(float v) {
    #pragma unroll
    for (int off = 16; off >= 1; off >>= 1)
        v = fmaxf(v, __shfl_xor_sync(0xffffffffu, v, off));
    return v;
}
__device__ __forceinline__ float warp_add(float v) {
    #pragma unroll
    for (int off = 16; off >= 1; off >>= 1)
        v += __shfl_xor_sync(0xffffffffu, v, off);
    return v;
}

// One-time prep: transpose W to o-contiguous dual-pairs, zero accumulators.
__global__ void prep_kernel(const float* __restrict__ w) {
    int idx = blockIdx.x * 256 + threadIdx.x;   // grid covers 32768
    if (idx < Ii * 4 * Oo) {
        int o = idx & 63, k = (idx >> 6) & 3, ic = idx >> 8;
        const float4 s = *(const float4*)(w + ((ic * Oo + o) * 16 + k * 4));
        ulonglong2 d;
        d.x = ((u64t)__float_as_uint(s.y) << 32) | __float_as_uint(s.x);
        d.y = ((u64t)__float_as_uint(s.w) << 32) | __float_as_uint(s.z);
        g_wT2[idx] = d;
    }
    float* s0 = &g_S0[0][0];
    float* s1 = &g_S1[0][0][0];
    float* s2 = &g_S2[0][0][0];
    if (idx < Bb * Oo) s0[idx] = 0.0f;
    if (idx < Bb * Oo * Pp) { s1[idx] = 0.0f; s2[idx] = 0.0f; }
}

// ============================================================================
// route_kernel: rr for one EM iteration. 256 thr = 8 warps = 4 spatial x
// 2 ic-halves (16 ic per warp) -> 4096 warps total -> ~40% occupancy.
// smem: mean(1280) inv(1280) ll(64) poseT(2048) act(128) = 4800 floats
// ============================================================================
__global__ __launch_bounds__(256, 3)
void route_kernel(const float* __restrict__ gpose,
                  const float* __restrict__ gact)
{
    __shared__ float sm[4800];
    float* sMean  = sm;            // negated mean, stride WS
    float* sInv   = sm + 1280;     // 1/(2 var), stride WS
    float* sLL    = sm + 2560;
    float* sPoseT = sm + 2624;     // [r][k][a] transposed pose
    float* sAct   = sm + 4672;

    const int tid   = threadIdx.x;
    const int b     = blockIdx.y;
    const int chunk = blockIdx.x;

    const float* gp = gpose + ((size_t)(b * Nn + chunk * ROWS)) * 16;
    for (int idx = tid; idx < ROWS * 16; idx += 256) {
        int r = idx >> 4, w16 = idx & 15, k = w16 >> 2, a = w16 & 3;
        sPoseT[idx] = gp[r * 16 + a * 4 + k];
    }
    for (int idx = tid; idx < ROWS; idx += 256)
        sAct[idx] = gact[b * Nn + chunk * ROWS + idx];
    for (int idx = tid; idx < Oo * Pp; idx += 256) {
        int o = idx >> 4, p = idx & 15;
        sMean[o * WS + p] = -g_mean[b][o][p];
        sInv[o * WS + p]  = g_inv2var[b][o][p];
    }
    if (tid < Oo) sLL[tid] = g_ll[b][tid];
    __syncthreads();

    const int wid  = tid >> 5;
    const int lane = tid & 31;
    const int spl  = wid >> 1;                 // local spatial 0..3
    const int ich  = (wid & 1) * 16;           // ic half: 0 or 16
    const int sp   = chunk * 4 + spl;
    const float chv = ((sp >> 3) + 0.5f) * 0.125f;
    const float cwv = ((sp & 7) + 0.5f) * 0.125f;

    const float ll0 = sLL[lane];
    const float ll1 = sLL[lane + 32];
    const ulonglong2* mra = (const ulonglong2*)&sMean[lane * WS];
    const ulonglong2* ira = (const ulonglong2*)&sInv[lane * WS];
    const ulonglong2* mrb = (const ulonglong2*)&sMean[(lane + 32) * WS];
    const ulonglong2* irb = (const ulonglong2*)&sInv[(lane + 32) * WS];

    float* rr_out = g_rrf + ((size_t)b * Nn + chunk * ROWS) * 64;

    for (int ic = ich; ic < ich + 16; ic++) {
        const int r = spl * 32 + ic;
        const float a_n = sAct[r];

        u64t va[8], vb[8];
        va[0] = pk2(chv, cwv);  vb[0] = va[0];
        #pragma unroll
        for (int r2 = 1; r2 < 8; r2++) { va[r2] = 0ull; vb[r2] = 0ull; }

        const ulonglong2* wb = g_wT2 + ic * 256;
        const float4* pT = (const float4*)&sPoseT[r * 16];
        #pragma unroll
        for (int k = 0; k < 4; k++) {
            ulonglong2 wk0 = __ldg(wb + k * 64 + lane);
            ulonglong2 wk1 = __ldg(wb + k * 64 + lane + 32);
            float4 pa4 = pT[k];
            float pav[4] = {pa4.x, pa4.y, pa4.z, pa4.w};
            #pragma unroll
            for (int a = 0; a < 4; a++) {
                u64t pa = pk2(pav[a], pav[a]);
                va[a*2+0] = fma2(pa, wk0.x, va[a*2+0]);
                va[a*2+1] = fma2(pa, wk0.y, va[a*2+1]);
                vb[a*2+0] = fma2(pa, wk1.x, vb[a*2+0]);
                vb[a*2+1] = fma2(pa, wk1.y, vb[a*2+1]);
            }
        }

        u64t acca = 0ull, accb = 0ull;
        #pragma unroll
        for (int q = 0; q < 4; q++) {
            ulonglong2 ma  = mra[q], iva = ira[q];
            ulonglong2 mb  = mrb[q], ivb = irb[q];
            u64t d0a = add2(va[q*2+0], ma.x);
            u64t d0b = add2(vb[q*2+0], mb.x);
            acca = fma2(mul2(d0a, d0a), iva.x, acca);
            accb = fma2(mul2(d0b, d0b), ivb.x, accb);
            u64t d1a = add2(va[q*2+1], ma.y);
            u64t d1b = add2(vb[q*2+1], mb.y);
            acca = fma2(mul2(d1a, d1a), iva.y, acca);
            accb = fma2(mul2(d1b, d1b), ivb.y, accb);
        }
        float al, ah, bl, bh;
        up2(acca, al, ah);
        up2(accb, bl, bh);
        float zz0 = ll0 - (al + ah);
        float zz1 = ll1 - (bl + bh);

        float m = warp_max(fmaxf(zz0, zz1));
        float e0 = __expf(zz0 - m);
        float e1 = __expf(zz1 - m);
        float s = warp_add(e0 + e1);
        float scale = __fdividef(a_n, s);

        rr_out[r * 64 + lane]      = e0 * scale;
        rr_out[r * 64 + lane + 32] = e1 * scale;
    }
}

// ============================================================================
// accum_kernel: votes + rr-weighted accumulation, one o-half per warp.
// 256 thr = 8 warps = 4 spatial x 2 o-halves. ~64 regs -> high occupancy.
// smem: poseT(2048) act(128) acc0(64) acc1(1088) acc2(1088) = 4416 floats
// ============================================================================
template<bool FIRST>
__global__ __launch_bounds__(256, 3)
void accum_kernel(const float* __restrict__ gpose,
                  const float* __restrict__ gact)
{
    __shared__ float sm[4416];
    float* sPoseT = sm;
    float* sAct   = sm + 2048;
    float* sAcc0  = sm + 2176;
    float* sAcc1  = sm + 2240;     // stride AS per o
    float* sAcc2  = sm + 3328;

    const int tid   = threadIdx.x;
    const int b     = blockIdx.y;
    const int chunk = blockIdx.x;

    const float* gp = gpose + ((size_t)(b * Nn + chunk * ROWS)) * 16;
    for (int idx = tid; idx < ROWS * 16; idx += 256) {
        int r = idx >> 4, w16 = idx & 15, k = w16 >> 2, a = w16 & 3;
        sPoseT[idx] = gp[r * 16 + a * 4 + k];
    }
    for (int idx = tid; idx < ROWS; idx += 256)
        sAct[idx] = gact[b * Nn + chunk * ROWS + idx];
    for (int idx = tid; idx < 64 + 2 * 1088; idx += 256) sAcc0[idx] = 0.0f;
    __syncthreads();

    const int wid  = tid >> 5;
    const int lane = tid & 31;
    const int spl  = wid >> 1;                 // local spatial 0..3
    const int half = wid & 1;                  // o half
    const int o    = half * 32 + lane;
    const int sp   = chunk * 4 + spl;
    const float chv = ((sp >> 3) + 0.5f) * 0.125f;
    const float cwv = ((sp & 7) + 0.5f) * 0.125f;

    const float* rr_in = g_rrf + ((size_t)b * Nn + chunk * ROWS) * 64;

    u64t A1[8], A2[8];
    float A0 = 0.0f;
    #pragma unroll
    for (int r2 = 0; r2 < 8; r2++) { A1[r2] = 0ull; A2[r2] = 0ull; }

    for (int ic = 0; ic < Ii; ic++) {
        const int r = spl * 32 + ic;

        float rrp;
        if (FIRST) {
            rrp = sAct[r] * (1.0f / 64.0f);
        } else {
            rrp = __ldg(&rr_in[r * 64 + o]);
        }

        u64t va[8];
        va[0] = pk2(chv, cwv);
        #pragma unroll
        for (int r2 = 1; r2 < 8; r2++) va[r2] = 0ull;

        const ulonglong2* wb = g_wT2 + ic * 256;
        const float4* pT = (const float4*)&sPoseT[r * 16];
        #pragma unroll
        for (int k = 0; k < 4; k++) {
            ulonglong2 wk = __ldg(wb + k * 64 + o);
            float4 pa4 = pT[k];
            float pav[4] = {pa4.x, pa4.y, pa4.z, pa4.w};
            #pragma unroll
            for (int a = 0; a < 4; a++) {
                u64t pa = pk2(pav[a], pav[a]);
                va[a*2+0] = fma2(pa, wk.x, va[a*2+0]);
                va[a*2+1] = fma2(pa, wk.y, va[a*2+1]);
            }
        }

        A0 += rrp;
        u64t rp = pk2(rrp, rrp);
        #pragma unroll
        for (int r2 = 0; r2 < 8; r2++) {
            u64t t = mul2(rp, va[r2]);
            A1[r2] = add2(A1[r2], t);
            A2[r2] = fma2(t, va[r2], A2[r2]);
        }
    }

    // cross-warp reduction (conflict-free smem atomics, stride AS)
    atomicAdd(&sAcc0[o], A0);
    #pragma unroll
    for (int r2 = 0; r2 < 8; r2++) {
        float l1, h1, l2h, h2h;
        up2(A1[r2], l1, h1);
        up2(A2[r2], l2h, h2h);
        atomicAdd(&sAcc1[o * AS + 2*r2],     l1);
        atomicAdd(&sAcc1[o * AS + 2*r2 + 1], h1);
        atomicAdd(&sAcc2[o * AS + 2*r2],     l2h);
        atomicAdd(&sAcc2[o * AS + 2*r2 + 1], h2h);
    }
    __syncthreads();

    float* gs0 = &g_S0[b][0];
    float* gs1 = &g_S1[b][0][0];
    float* gs2 = &g_S2[b][0][0];
    for (int idx = tid; idx < Oo; idx += 256) atomicAdd(&gs0[idx], sAcc0[idx]);
    for (int idx = tid; idx < Oo * Pp; idx += 256) {
        int oo = idx >> 4, p = idx & 15;
        atomicAdd(&gs1[idx], sAcc1[oo * AS + p]);
        atomicAdd(&gs2[idx], sAcc2[oo * AS + p]);
    }
}

__global__ __launch_bounds__(64)
void finalize_kernel(int it,
                     const float* __restrict__ beta_v,
                     const float* __restrict__ beta_a,
                     float* __restrict__ out)
{
    __shared__ float sCost[Oo];
    const int b = blockIdx.x;
    const int o = threadIdx.x;

    const float rps = g_S0[b][o];
    const float inv_rps = 1.0f / rps;
    float mean[16], inv2v[16];
    float lsum = 0.0f;
    #pragma unroll
    for (int p = 0; p < 16; p++) {
        float m = g_S1[b][o][p] * inv_rps;
        float var = g_S2[b][o][p] * inv_rps - m * m;
        var = fmaxf(var, 0.0f);
        float sd = sqrtf(var);
        mean[p] = m;
        inv2v[p] = 0.5f / var;
        lsum += __logf(sd + EPSF);
    }
    const float cost = (16.0f * beta_v[o] + lsum) * rps;
    sCost[o] = cost;
    __syncthreads();

    float cm = 0.0f;
    for (int q = 0; q < Oo; q++) cm += sCost[q];
    cm *= (1.0f / 64.0f);
    float cv = 0.0f;
    for (int q = 0; q < Oo; q++) { float d = sCost[q] - cm; cv += d * d; }
    const float cstd = sqrtf(cv * (1.0f / 64.0f));

    const float inv_temp = 1.0f + (float)it;
    const float x = inv_temp * (beta_a[o] + (cm - cost) / (cstd + EPSF));
    const float oact = 1.0f / (1.0f + __expf(-x));

    if (it < 2) {
        g_ll[b][o] = __logf(oact + EPSF) - lsum;
        #pragma unroll
        for (int p = 0; p < 16; p++) {
            g_mean[b][o][p] = mean[p];
            g_inv2var[b][o][p] = inv2v[p];
        }
        g_S0[b][o] = 0.0f;
        #pragma unroll
        for (int p = 0; p < 16; p++) { g_S1[b][o][p] = 0.0f; g_S2[b][o][p] = 0.0f; }
    } else {
        #pragma unroll
        for (int p = 0; p < 16; p++) out[(b * Oo + o) * 16 + p] = mean[p];
        out[Bb * Oo * Pp + b * Oo + o] = oact;
    }
}

extern "C" void kernel_launch(void* const* d_in, const int* in_sizes, int n_in,
                              void* d_out, int out_size)
{
    const float* pose = (const float*)d_in[0];
    const float* act  = (const float*)d_in[1];
    const float* w    = (const float*)d_in[2];
    const float* bv   = (const float*)d_in[3];
    const float* ba   = (const float*)d_in[4];
    float* out = (float*)d_out;

    dim3 grid(CHUNKS, Bb);

    prep_kernel<<<128, 256>>>(w);
    accum_kernel<true><<<grid, 256>>>(pose, act);
    finalize_kernel<<<Bb, 64>>>(0, bv, ba, out);
    route_kernel<<<grid, 256>>>(pose, act);
    accum_kernel<false><<<grid, 256>>>(pose, act);
    finalize_kernel<<<Bb, 64>>>(1, bv, ba, out);
    route_kernel<<<grid, 256>>>(pose, act);
    accum_kernel<false><<<grid, 256>>>(pose, act);
    finalize_kernel<<<Bb, 64>>>(2, bv, ba, out);
}

// round 13
// speedup vs baseline: 1.4179x; 1.4179x over previous
#include <cuda_runtime.h>
#include <cstdint>

#define EPSF 1e-7f
typedef unsigned long long u64t;

constexpr int Bb = 32;
constexpr int Ii = 32;
constexpr int Oo = 64;
constexpr int Pp = 16;
constexpr int Nn = 2048;
constexpr int CHUNKS = 16;   // 4 spatial per block
constexpr int ROWS = 128;    // 4 spatial * 32 i
constexpr int WS = 20;       // padded stride for mean/inv (conflict-free LDS128)
constexpr int REC = 33;      // floats per (o) partial record: A0 + 16 A1 + 16 A2

// Global scratch (device globals; no cudaMalloc allowed)
__device__ float g_mean[Bb][Oo][Pp];
__device__ float g_inv2var[Bb][Oo][Pp];
__device__ float g_ll[Bb][Oo];              // log(act+eps) - lsum (fused)
__device__ ulonglong2 g_wT2[Ii * 4 * Oo];   // W: [ic][k][o] -> {pair(c0,c1), pair(c2,c3)}
__device__ float g_part[(size_t)Bb * CHUNKS * Oo * REC];   // per-(b,chunk) partials

// ---- f32x2 packed helpers ----
__device__ __forceinline__ u64t pk2(float lo, float hi) {
    u64t r; asm("mov.b64 %0,{%1,%2};" : "=l"(r) : "f"(lo), "f"(hi)); return r;
}
__device__ __forceinline__ void up2(u64t a, float& lo, float& hi) {
    asm("mov.b64 {%0,%1},%2;" : "=f"(lo), "=f"(hi) : "l"(a));
}
__device__ __forceinline__ u64t fma2(u64t a, u64t b, u64t c) {
    u64t d; asm("fma.rn.f32x2 %0,%1,%2,%3;" : "=l"(d) : "l"(a), "l"(b), "l"(c)); return d;
}
__device__ __forceinline__ u64t add2(u64t a, u64t b) {
    u64t d; asm("add.rn.f32x2 %0,%1,%2;" : "=l"(d) : "l"(a), "l"(b)); return d;
}
__device__ __forceinline__ u64t mul2(u64t a, u64t b) {
    u64t d; asm("mul.rn.f32x2 %0,%1,%2;" : "=l"(d) : "l"(a), "l"(b)); return d;
}
// ---- warp reductions (redux.sync.f32 not in sm_103 ISA) ----
__device__ __forceinline__ float warp_max(float v) {
    #pragma unroll
    for (int off = 16; off >= 1; off >>= 1)
        v = fmaxf(v, __shfl_xor_sync(0xffffffffu, v, off));
    return v;
}
__device__ __forceinline__ float warp_add(float v) {
    #pragma unroll
    for (int off = 16; off >= 1; off >>= 1)
        v += __shfl_xor_sync(0xffffffffu, v, off);
    return v;
}

// One-time prep: transpose W to o-contiguous dual-pairs.
__global__ void prep_kernel(const float* __restrict__ w) {
    int idx = blockIdx.x * 256 + threadIdx.x;   // grid covers 8192
    if (idx < Ii * 4 * Oo) {
        int o = idx & 63, k = (idx >> 6) & 3, ic = idx >> 8;
        const float4 s = *(const float4*)(w + ((ic * Oo + o) * 16 + k * 4));
        ulonglong2 d;
        d.x = ((u64t)__float_as_uint(s.y) << 32) | __float_as_uint(s.x);
        d.y = ((u64t)__float_as_uint(s.w) << 32) | __float_as_uint(s.z);
        g_wT2[idx] = d;
    }
}

// Fused stats kernel. 128 thr = 4 warps = 4 spatial; each warp covers both
// o-halves with MLP=8 paired loads. NO ATOMICS: partials -> smem STS ->
// 4-way tree sum -> plain coalesced STG to per-(b,chunk) slot.
// smem = max(main 7040-ish, partials 4*64*33=8448 floats) -> 8448 (33KB)
template<bool FIRST>
__global__ __launch_bounds__(128, 4)
void stats_kernel(const float* __restrict__ gpose,
                  const float* __restrict__ gact)
{
    __shared__ float sm[8448];
    float* sMean = sm;             // negated mean, stride WS (1280)
    float* sInv  = sm + 1280;      // 1/(2 var), stride WS (1280)
    float* sLL   = sm + 2560;      // (64)
    float* sPose = sm + 2624;      // (2048)
    float* sAct  = sm + 4672;      // (128)

    const int tid   = threadIdx.x;
    const int b     = blockIdx.y;
    const int chunk = blockIdx.x;

    // ---- stage pose + act ----
    const float4* gp4 = (const float4*)(gpose + ((size_t)(b * Nn + chunk * ROWS)) * 16);
    #pragma unroll
    for (int i = 0; i < 4; i++)
        ((float4*)sPose)[tid + 128 * i] = gp4[tid + 128 * i];
    sAct[tid] = gact[b * Nn + chunk * ROWS + tid];

    if (!FIRST) {
        for (int idx = tid; idx < Oo * Pp; idx += 128) {
            int o = idx >> 4, p = idx & 15;
            sMean[o * WS + p] = -g_mean[b][o][p];
            sInv[o * WS + p]  = g_inv2var[b][o][p];
        }
        if (tid < Oo) sLL[tid] = g_ll[b][tid];
    }
    __syncthreads();

    const int wid  = tid >> 5;
    const int lane = tid & 31;
    const int sp   = chunk * 4 + wid;              // global spatial [0,64)
    const float chv = ((sp >> 3) + 0.5f) * 0.125f;
    const float cwv = ((sp & 7) + 0.5f) * 0.125f;

    float ll0 = 0.0f, ll1 = 0.0f;
    if (!FIRST) { ll0 = sLL[lane]; ll1 = sLL[lane + 32]; }

    u64t A1[2][8], A2[2][8];
    float A0[2] = {0.0f, 0.0f};
    #pragma unroll
    for (int j = 0; j < 2; j++)
        #pragma unroll
        for (int r2 = 0; r2 < 8; r2++) { A1[j][r2] = 0ull; A2[j][r2] = 0ull; }

    for (int ic = 0; ic < Ii; ic++) {
        const int r = wid * 32 + ic;

        float pr[16];
        {
            const float4* pp = (const float4*)&sPose[r * 16];
            #pragma unroll
            for (int q = 0; q < 4; q++) {
                float4 t = pp[q];
                pr[q*4+0] = t.x; pr[q*4+1] = t.y; pr[q*4+2] = t.z; pr[q*4+3] = t.w;
            }
        }
        const float a_n = sAct[r];

        // votes for BOTH o-halves, loads paired per k (MLP=8)
        u64t va[8], vb[8];
        va[0] = pk2(chv, cwv);  vb[0] = va[0];
        #pragma unroll
        for (int r2 = 1; r2 < 8; r2++) { va[r2] = 0ull; vb[r2] = 0ull; }

        const ulonglong2* wb = g_wT2 + ic * 256;
        #pragma unroll
        for (int k = 0; k < 4; k++) {
            ulonglong2 wk0 = __ldg(wb + k * 64 + lane);
            ulonglong2 wk1 = __ldg(wb + k * 64 + lane + 32);
            #pragma unroll
            for (int a = 0; a < 4; a++) {
                u64t pa = pk2(pr[a*4+k], pr[a*4+k]);
                va[a*2+0] = fma2(pa, wk0.x, va[a*2+0]);
                va[a*2+1] = fma2(pa, wk0.y, va[a*2+1]);
                vb[a*2+0] = fma2(pa, wk1.x, vb[a*2+0]);
                vb[a*2+1] = fma2(pa, wk1.y, vb[a*2+1]);
            }
        }

        float zz0 = 0.0f, zz1 = 0.0f;
        if (!FIRST) {
            u64t acca = 0ull, accb = 0ull;
            const ulonglong2* mra = (const ulonglong2*)&sMean[lane * WS];
            const ulonglong2* ira = (const ulonglong2*)&sInv[lane * WS];
            const ulonglong2* mrb = (const ulonglong2*)&sMean[(lane + 32) * WS];
            const ulonglong2* irb = (const ulonglong2*)&sInv[(lane + 32) * WS];
            #pragma unroll
            for (int q = 0; q < 4; q++) {
                ulonglong2 ma  = mra[q], iva = ira[q];
                ulonglong2 mb  = mrb[q], ivb = irb[q];
                u64t d0a = add2(va[q*2+0], ma.x);
                u64t d0b = add2(vb[q*2+0], mb.x);
                acca = fma2(mul2(d0a, d0a), iva.x, acca);
                accb = fma2(mul2(d0b, d0b), ivb.x, accb);
                u64t d1a = add2(va[q*2+1], ma.y);
                u64t d1b = add2(vb[q*2+1], mb.y);
                acca = fma2(mul2(d1a, d1a), iva.y, acca);
                accb = fma2(mul2(d1b, d1b), ivb.y, accb);
            }
            float al, ah, bl, bh;
            up2(acca, al, ah);
            up2(accb, bl, bh);
            zz0 = ll0 - (al + ah);
            zz1 = ll1 - (bl + bh);
        }

        float rrp0, rrp1;
        if (!FIRST) {
            float m = warp_max(fmaxf(zz0, zz1));
            float e0 = __expf(zz0 - m);
            float e1 = __expf(zz1 - m);
            float s = warp_add(e0 + e1);
            float scale = __fdividef(a_n, s);
            rrp0 = e0 * scale;
            rrp1 = e1 * scale;
        } else {
            rrp0 = rrp1 = a_n * (1.0f / 64.0f);
        }

        A0[0] += rrp0;
        A0[1] += rrp1;
        u64t rp0 = pk2(rrp0, rrp0);
        u64t rp1 = pk2(rrp1, rrp1);
        #pragma unroll
        for (int r2 = 0; r2 < 8; r2++) {
            u64t ta = mul2(rp0, va[r2]);
            u64t tb = mul2(rp1, vb[r2]);
            A1[0][r2] = add2(A1[0][r2], ta);
            A1[1][r2] = add2(A1[1][r2], tb);
            A2[0][r2] = fma2(ta, va[r2], A2[0][r2]);
            A2[1][r2] = fma2(tb, vb[r2], A2[1][r2]);
        }
    }

    // ---- NO-ATOMIC reduction: STS partials, tree-sum, plain STG ----
    __syncthreads();               // everyone done with sMean/sPose etc.
    float* sPart = sm;             // reuse ALL smem: [w][o][REC]
    #pragma unroll
    for (int j2 = 0; j2 < 2; j2++) {
        const int o = lane + 32 * j2;
        float* rec = &sPart[(wid * Oo + o) * REC];
        rec[0] = A0[j2];
        #pragma unroll
        for (int r2 = 0; r2 < 8; r2++) {
            float lo, hi;
            up2(A1[j2][r2], lo, hi);
            rec[1 + 2*r2]  = lo;
            rec[2 + 2*r2]  = hi;
            up2(A2[j2][r2], lo, hi);
            rec[17 + 2*r2] = lo;
            rec[18 + 2*r2] = hi;
        }
    }
    __syncthreads();

    float* gout = g_part + ((size_t)(b * CHUNKS + chunk)) * (Oo * REC);
    for (int e = tid; e < Oo * REC; e += 128) {
        float s = sPart[e] + sPart[Oo * REC + e]
                + sPart[2 * Oo * REC + e] + sPart[3 * Oo * REC + e];
        gout[e] = s;
    }
}

// finalize: sum 16 chunk partials per (b,o), then EM finalize math.
__global__ __launch_bounds__(64)
void finalize_kernel(int it,
                     const float* __restrict__ beta_v,
                     const float* __restrict__ beta_a,
                     float* __restrict__ out)
{
    __shared__ float sCost[Oo];
    const int b = blockIdx.x;
    const int o = threadIdx.x;

    const float* pb = g_part + (size_t)b * CHUNKS * (Oo * REC) + o * REC;
    float s0 = 0.0f;
    float s1[16], s2[16];
    #pragma unroll
    for (int p = 0; p < 16; p++) { s1[p] = 0.0f; s2[p] = 0.0f; }
    for (int ch = 0; ch < CHUNKS; ch++) {
        const float* rec = pb + ch * (Oo * REC);
        s0 += __ldg(&rec[0]);
        #pragma unroll
        for (int p = 0; p < 16; p++) {
            s1[p] += __ldg(&rec[1 + p]);
            s2[p] += __ldg(&rec[17 + p]);
        }
    }

    const float inv_rps = 1.0f / s0;
    float mean[16], inv2v[16];
    float lsum = 0.0f;
    #pragma unroll
    for (int p = 0; p < 16; p++) {
        float m = s1[p] * inv_rps;
        float var = s2[p] * inv_rps - m * m;
        var = fmaxf(var, 0.0f);
        float sd = sqrtf(var);
        mean[p] = m;
        inv2v[p] = 0.5f / var;
        lsum += __logf(sd + EPSF);
    }
    const float cost = (16.0f * beta_v[o] + lsum) * s0;
    sCost[o] = cost;
    __syncthreads();

    float cm = 0.0f;
    for (int q = 0; q < Oo; q++) cm += sCost[q];
    cm *= (1.0f / 64.0f);
    float cv = 0.0f;
    for (int q = 0; q < Oo; q++) { float d = sCost[q] - cm; cv += d * d; }
    const float cstd = sqrtf(cv * (1.0f / 64.0f));

    const float inv_temp = 1.0f + (float)it;
    const float x = inv_temp * (beta_a[o] + (cm - cost) / (cstd + EPSF));
    const float oact = 1.0f / (1.0f + __expf(-x));

    if (it < 2) {
        g_ll[b][o] = __logf(oact + EPSF) - lsum;
        #pragma unroll
        for (int p = 0; p < 16; p++) {
            g_mean[b][o][p] = mean[p];
            g_inv2var[b][o][p] = inv2v[p];
        }
    } else {
        #pragma unroll
        for (int p = 0; p < 16; p++) out[(b * Oo + o) * 16 + p] = mean[p];
        out[Bb * Oo * Pp + b * Oo + o] = oact;
    }
}

extern "C" void kernel_launch(void* const* d_in, const int* in_sizes, int n_in,
                              void* d_out, int out_size)
{
    const float* pose = (const float*)d_in[0];
    const float* act  = (const float*)d_in[1];
    const float* w    = (const float*)d_in[2];
    const float* bv   = (const float*)d_in[3];
    const float* ba   = (const float*)d_in[4];
    float* out = (float*)d_out;

    dim3 grid(CHUNKS, Bb);

    prep_kernel<<<32, 256>>>(w);
    stats_kernel<true><<<grid, 128>>>(pose, act);
    finalize_kernel<<<Bb, 64>>>(0, bv, ba, out);
    stats_kernel<false><<<grid, 128>>>(pose, act);
    finalize_kernel<<<Bb, 64>>>(1, bv, ba, out);
    stats_kernel<false><<<grid, 128>>>(pose, act);
    finalize_kernel<<<Bb, 64>>>(2, bv, ba, out);
}

// round 14
// speedup vs baseline: 1.5818x; 1.1156x over previous
#include <cuda_runtime.h>
#include <cstdint>

#define EPSF 1e-7f
typedef unsigned long long u64t;

constexpr int Bb = 32;
constexpr int Ii = 32;
constexpr int Oo = 64;
constexpr int Pp = 16;
constexpr int Nn = 2048;
constexpr int CHUNKS = 16;   // 4 spatial per block
constexpr int ROWS = 128;    // 4 spatial * 32 i
constexpr int WS = 20;       // padded stride for mean/inv (conflict-free LDS128)
constexpr int REC = 33;      // floats per (o) partial record: A0 + 16 A1 + 16 A2

// Global scratch (device globals; no cudaMalloc allowed)
__device__ float g_mean[Bb][Oo][Pp];
__device__ float g_inv2var[Bb][Oo][Pp];
__device__ float g_ll[Bb][Oo];              // log(act+eps) - lsum - max_o(.)  (pre-shifted)
__device__ ulonglong2 g_wT2[Ii * 4 * Oo];   // W: [ic][k][o] -> {pair(c0,c1), pair(c2,c3)}
__device__ float g_part[(size_t)Bb * CHUNKS * Oo * REC];   // per-(b,chunk) partials

// ---- f32x2 packed helpers ----
__device__ __forceinline__ u64t pk2(float lo, float hi) {
    u64t r; asm("mov.b64 %0,{%1,%2};" : "=l"(r) : "f"(lo), "f"(hi)); return r;
}
__device__ __forceinline__ void up2(u64t a, float& lo, float& hi) {
    asm("mov.b64 {%0,%1},%2;" : "=f"(lo), "=f"(hi) : "l"(a));
}
__device__ __forceinline__ u64t fma2(u64t a, u64t b, u64t c) {
    u64t d; asm("fma.rn.f32x2 %0,%1,%2,%3;" : "=l"(d) : "l"(a), "l"(b), "l"(c)); return d;
}
__device__ __forceinline__ u64t add2(u64t a, u64t b) {
    u64t d; asm("add.rn.f32x2 %0,%1,%2;" : "=l"(d) : "l"(a), "l"(b)); return d;
}
__device__ __forceinline__ u64t mul2(u64t a, u64t b) {
    u64t d; asm("mul.rn.f32x2 %0,%1,%2;" : "=l"(d) : "l"(a), "l"(b)); return d;
}
// ---- warp sum reduction (redux.sync.f32 not in sm_103 ISA) ----
__device__ __forceinline__ float warp_add(float v) {
    #pragma unroll
    for (int off = 16; off >= 1; off >>= 1)
        v += __shfl_xor_sync(0xffffffffu, v, off);
    return v;
}

// One-time prep: transpose W to o-contiguous dual-pairs.
__global__ void prep_kernel(const float* __restrict__ w) {
    int idx = blockIdx.x * 256 + threadIdx.x;   // grid covers 8192
    if (idx < Ii * 4 * Oo) {
        int o = idx & 63, k = (idx >> 6) & 3, ic = idx >> 8;
        const float4 s = *(const float4*)(w + ((ic * Oo + o) * 16 + k * 4));
        ulonglong2 d;
        d.x = ((u64t)__float_as_uint(s.y) << 32) | __float_as_uint(s.x);
        d.y = ((u64t)__float_as_uint(s.w) << 32) | __float_as_uint(s.z);
        g_wT2[idx] = d;
    }
}

// Fused stats kernel. 128 thr = 4 warps = 4 spatial; each warp covers both
// o-halves with MLP=8 paired loads. No atomics, no warp_max (g_ll is
// pre-shifted so zz <= 0 and exp is overflow-safe).
template<bool FIRST>
__global__ __launch_bounds__(128, 4)
void stats_kernel(const float* __restrict__ gpose,
                  const float* __restrict__ gact)
{
    __shared__ float sm[8448];
    float* sMean = sm;             // negated mean, stride WS (1280)
    float* sInv  = sm + 1280;      // 1/(2 var), stride WS (1280)
    float* sLL   = sm + 2560;      // (64)
    float* sPose = sm + 2624;      // (2048)
    float* sAct  = sm + 4672;      // (128)

    const int tid   = threadIdx.x;
    const int b     = blockIdx.y;
    const int chunk = blockIdx.x;

    // ---- stage pose + act ----
    const float4* gp4 = (const float4*)(gpose + ((size_t)(b * Nn + chunk * ROWS)) * 16);
    #pragma unroll
    for (int i = 0; i < 4; i++)
        ((float4*)sPose)[tid + 128 * i] = gp4[tid + 128 * i];
    sAct[tid] = gact[b * Nn + chunk * ROWS + tid];

    if (!FIRST) {
        for (int idx = tid; idx < Oo * Pp; idx += 128) {
            int o = idx >> 4, p = idx & 15;
            sMean[o * WS + p] = -g_mean[b][o][p];
            sInv[o * WS + p]  = g_inv2var[b][o][p];
        }
        if (tid < Oo) sLL[tid] = g_ll[b][tid];
    }
    __syncthreads();

    const int wid  = tid >> 5;
    const int lane = tid & 31;
    const int sp   = chunk * 4 + wid;              // global spatial [0,64)
    const float chv = ((sp >> 3) + 0.5f) * 0.125f;
    const float cwv = ((sp & 7) + 0.5f) * 0.125f;

    float ll0 = 0.0f, ll1 = 0.0f;
    if (!FIRST) { ll0 = sLL[lane]; ll1 = sLL[lane + 32]; }

    u64t A1[2][8], A2[2][8];
    float A0[2] = {0.0f, 0.0f};
    #pragma unroll
    for (int j = 0; j < 2; j++)
        #pragma unroll
        for (int r2 = 0; r2 < 8; r2++) { A1[j][r2] = 0ull; A2[j][r2] = 0ull; }

    for (int ic = 0; ic < Ii; ic++) {
        const int r = wid * 32 + ic;

        float pr[16];
        {
            const float4* pp = (const float4*)&sPose[r * 16];
            #pragma unroll
            for (int q = 0; q < 4; q++) {
                float4 t = pp[q];
                pr[q*4+0] = t.x; pr[q*4+1] = t.y; pr[q*4+2] = t.z; pr[q*4+3] = t.w;
            }
        }
        const float a_n = sAct[r];

        // votes for BOTH o-halves, loads paired per k (MLP=8)
        u64t va[8], vb[8];
        va[0] = pk2(chv, cwv);  vb[0] = va[0];
        #pragma unroll
        for (int r2 = 1; r2 < 8; r2++) { va[r2] = 0ull; vb[r2] = 0ull; }

        const ulonglong2* wb = g_wT2 + ic * 256;
        #pragma unroll
        for (int k = 0; k < 4; k++) {
            ulonglong2 wk0 = __ldg(wb + k * 64 + lane);
            ulonglong2 wk1 = __ldg(wb + k * 64 + lane + 32);
            #pragma unroll
            for (int a = 0; a < 4; a++) {
                u64t pa = pk2(pr[a*4+k], pr[a*4+k]);
                va[a*2+0] = fma2(pa, wk0.x, va[a*2+0]);
                va[a*2+1] = fma2(pa, wk0.y, va[a*2+1]);
                vb[a*2+0] = fma2(pa, wk1.x, vb[a*2+0]);
                vb[a*2+1] = fma2(pa, wk1.y, vb[a*2+1]);
            }
        }

        float rrp0, rrp1;
        if (!FIRST) {
            u64t acca = 0ull, accb = 0ull;
            const ulonglong2* mra = (const ulonglong2*)&sMean[lane * WS];
            const ulonglong2* ira = (const ulonglong2*)&sInv[lane * WS];
            const ulonglong2* mrb = (const ulonglong2*)&sMean[(lane + 32) * WS];
            const ulonglong2* irb = (const ulonglong2*)&sInv[(lane + 32) * WS];
            #pragma unroll
            for (int q = 0; q < 4; q++) {
                ulonglong2 ma  = mra[q], iva = ira[q];
                ulonglong2 mb  = mrb[q], ivb = irb[q];
                u64t d0a = add2(va[q*2+0], ma.x);
                u64t d0b = add2(vb[q*2+0], mb.x);
                acca = fma2(mul2(d0a, d0a), iva.x, acca);
                accb = fma2(mul2(d0b, d0b), ivb.x, accb);
                u64t d1a = add2(va[q*2+1], ma.y);
                u64t d1b = add2(vb[q*2+1], mb.y);
                acca = fma2(mul2(d1a, d1a), iva.y, acca);
                accb = fma2(mul2(d1b, d1b), ivb.y, accb);
            }
            float al, ah, bl, bh;
            up2(acca, al, ah);
            up2(accb, bl, bh);
            // g_ll pre-shifted by max_o -> zz <= 0, exp safe with no warp max
            float e0 = __expf(ll0 - (al + ah));
            float e1 = __expf(ll1 - (bl + bh));
            float s = warp_add(e0 + e1);
            float scale = __fdividef(a_n, s);
            rrp0 = e0 * scale;
            rrp1 = e1 * scale;
        } else {
            rrp0 = rrp1 = a_n * (1.0f / 64.0f);
        }

        A0[0] += rrp0;
        A0[1] += rrp1;
        u64t rp0 = pk2(rrp0, rrp0);
        u64t rp1 = pk2(rrp1, rrp1);
        #pragma unroll
        for (int r2 = 0; r2 < 8; r2++) {
            u64t ta = mul2(rp0, va[r2]);
            u64t tb = mul2(rp1, vb[r2]);
            A1[0][r2] = add2(A1[0][r2], ta);
            A1[1][r2] = add2(A1[1][r2], tb);
            A2[0][r2] = fma2(ta, va[r2], A2[0][r2]);
            A2[1][r2] = fma2(tb, vb[r2], A2[1][r2]);
        }
    }

    // ---- NO-ATOMIC reduction: STS partials, tree-sum, plain STG ----
    __syncthreads();               // everyone done with sMean/sPose etc.
    float* sPart = sm;             // reuse ALL smem: [w][o][REC]
    #pragma unroll
    for (int j2 = 0; j2 < 2; j2++) {
        const int o = lane + 32 * j2;
        float* rec = &sPart[(wid * Oo + o) * REC];
        rec[0] = A0[j2];
        #pragma unroll
        for (int r2 = 0; r2 < 8; r2++) {
            float lo, hi;
            up2(A1[j2][r2], lo, hi);
            rec[1 + 2*r2]  = lo;
            rec[2 + 2*r2]  = hi;
            up2(A2[j2][r2], lo, hi);
            rec[17 + 2*r2] = lo;
            rec[18 + 2*r2] = hi;
        }
    }
    __syncthreads();

    float* gout = g_part + ((size_t)(b * CHUNKS + chunk)) * (Oo * REC);
    for (int e = tid; e < Oo * REC; e += 128) {
        float s = sPart[e] + sPart[Oo * REC + e]
                + sPart[2 * Oo * REC + e] + sPart[3 * Oo * REC + e];
        gout[e] = s;
    }
}

// finalize: sum 16 chunk partials per (b,o), then EM finalize math.
// Stores g_ll pre-shifted by its per-batch max so stats needs no warp_max.
__global__ __launch_bounds__(64)
void finalize_kernel(int it,
                     const float* __restrict__ beta_v,
                     const float* __restrict__ beta_a,
                     float* __restrict__ out)
{
    __shared__ float sCost[Oo];
    __shared__ float sLLs[Oo];
    const int b = blockIdx.x;
    const int o = threadIdx.x;

    const float* pb = g_part + (size_t)b * CHUNKS * (Oo * REC) + o * REC;
    float s0 = 0.0f;
    float s1[16], s2[16];
    #pragma unroll
    for (int p = 0; p < 16; p++) { s1[p] = 0.0f; s2[p] = 0.0f; }
    for (int ch = 0; ch < CHUNKS; ch++) {
        const float* rec = pb + ch * (Oo * REC);
        s0 += __ldg(&rec[0]);
        #pragma unroll
        for (int p = 0; p < 16; p++) {
            s1[p] += __ldg(&rec[1 + p]);
            s2[p] += __ldg(&rec[17 + p]);
        }
    }

    const float inv_rps = 1.0f / s0;
    float mean[16], inv2v[16];
    float lsum = 0.0f;
    #pragma unroll
    for (int p = 0; p < 16; p++) {
        float m = s1[p] * inv_rps;
        float var = s2[p] * inv_rps - m * m;
        var = fmaxf(var, 0.0f);
        float sd = sqrtf(var);
        mean[p] = m;
        inv2v[p] = 0.5f / var;
        lsum += __logf(sd + EPSF);
    }
    const float cost = (16.0f * beta_v[o] + lsum) * s0;
    sCost[o] = cost;
    __syncthreads();

    float cm = 0.0f;
    for (int q = 0; q < Oo; q++) cm += sCost[q];
    cm *= (1.0f / 64.0f);
    float cv = 0.0f;
    for (int q = 0; q < Oo; q++) { float d = sCost[q] - cm; cv += d * d; }
    const float cstd = sqrtf(cv * (1.0f / 64.0f));

    const float inv_temp = 1.0f + (float)it;
    const float x = inv_temp * (beta_a[o] + (cm - cost) / (cstd + EPSF));
    const float oact = 1.0f / (1.0f + __expf(-x));

    if (it < 2) {
        const float llv = __logf(oact + EPSF) - lsum;
        sLLs[o] = llv;
        #pragma unroll
        for (int p = 0; p < 16; p++) {
            g_mean[b][o][p] = mean[p];
            g_inv2var[b][o][p] = inv2v[p];
        }
        __syncthreads();
        float M = sLLs[0];
        for (int q = 1; q < Oo; q++) M = fmaxf(M, sLLs[q]);
        g_ll[b][o] = llv - M;     // pre-shift: zz = ll - dist <= 0 in stats
    } else {
        #pragma unroll
        for (int p = 0; p < 16; p++) out[(b * Oo + o) * 16 + p] = mean[p];
        out[Bb * Oo * Pp + b * Oo + o] = oact;
    }
}

extern "C" void kernel_launch(void* const* d_in, const int* in_sizes, int n_in,
                              void* d_out, int out_size)
{
    const float* pose = (const float*)d_in[0];
    const float* act  = (const float*)d_in[1];
    const float* w    = (const float*)d_in[2];
    const float* bv   = (const float*)d_in[3];
    const float* ba   = (const float*)d_in[4];
    float* out = (float*)d_out;

    dim3 grid(CHUNKS, Bb);

    prep_kernel<<<32, 256>>>(w);
    stats_kernel<true><<<grid, 128>>>(pose, act);
    finalize_kernel<<<Bb, 64>>>(0, bv, ba, out);
    stats_kernel<false><<<grid, 128>>>(pose, act);
    finalize_kernel<<<Bb, 64>>>(1, bv, ba, out);
    stats_kernel<false><<<grid, 128>>>(pose, act);
    finalize_kernel<<<Bb, 64>>>(2, bv, ba, out);
}